// round 6
// baseline (speedup 1.0000x reference)
#include <cuda_runtime.h>

// ---------------- problem constants ----------------
#define NZ     300
#define NX     400
#define NPML   32
#define NZP    (NZ + 2*NPML)            // 364
#define NXP    (NX + 2*NPML)            // 464
#define NXPP   480                      // global row pitch (floats)
#define NSTEPS 200
#define NSHOTS 2
#define DXC    0.01f
#define DTC    0.001f
#define SRC_Z  (NPML + 2)               // 34
#define REC_Z  (NPML + 2)               // 34

#define FSZ (NZP * NXPP)

#define BLKS_PER_SHOT 74
#define NBLK   (NSHOTS * BLKS_PER_SHOT) // 148
#define NTHR   1024
#define MAXC   3

// smem tile rows: r0=z0-2, r1=z0-1, owned r2..nrows+1, r(nrows+2)=z1, r(nrows+3)=z1+1
#define SROWS  9
#define SPITCH 480
#define FTILE  (SROWS * SPITCH)
#define SMEM_DYN (5 * FTILE * 4)        // 86400 B

// flag bits
#define F_VAL  1
#define F_REC  2
#define F_SRC  4
#define F_PXX  8     // publish sxx
#define F_PZZ  16    // publish szz
#define F_PXZ  32    // publish sxz

// ---------------- device state (static, no allocs) ----------------
// parity double-buffered stress exchange (only boundary rows ever touched)
__device__ float g_bsxx[2][NSHOTS][FSZ];
__device__ float g_bszz[2][NSHOTS][FSZ];
__device__ float g_bsxz[2][NSHOTS][FSZ];

__device__ unsigned g_flags[NBLK * 32];   // monotonic, 128B apart
__device__ double   g_part[NBLK];
__device__ unsigned g_done = 0u;

__device__ __forceinline__ void st_release_u32(unsigned* p, unsigned v)
{
    asm volatile("st.release.gpu.global.u32 [%0], %1;" :: "l"(p), "r"(v) : "memory");
}
__device__ __forceinline__ unsigned ld_acquire_u32(const unsigned* p)
{
    unsigned v;
    asm volatile("ld.acquire.gpu.global.u32 %0, [%1];" : "=r"(v) : "l"(p) : "memory");
    return v;
}
__device__ __forceinline__ void wait_flag(const unsigned* f, unsigned q)
{
    while ((int)(ld_acquire_u32(f) - q) < 0) { }
}

__global__ void __launch_bounds__(NTHR, 1)
fwi_persistent(const float* __restrict__ Vp,
               const float* __restrict__ Vs,
               const float* __restrict__ Den,
               const float* __restrict__ Stf,
               const float* __restrict__ Mask,
               const int*   __restrict__ ShotIds,
               float*       __restrict__ out)
{
    extern __shared__ float sm[];
    float* __restrict__ s_vx  = sm;
    float* __restrict__ s_vz  = sm + 1 * FTILE;
    float* __restrict__ s_sxx = sm + 2 * FTILE;
    float* __restrict__ s_szz = sm + 3 * FTILE;
    float* __restrict__ s_sxz = sm + 4 * FTILE;

    const int b   = blockIdx.x;
    const int s   = b / BLKS_PER_SHOT;
    const int kk  = b - s * BLKS_PER_SHOT;
    const int z0  = (kk * NZP) / BLKS_PER_SHOT;
    const int z1  = ((kk + 1) * NZP) / BLKS_PER_SHOT;
    const int nrows  = z1 - z0;
    const int ncells = nrows * NXP;
    const int tid = threadIdx.x;

    const int nb_lo = (kk > 0)                 ? b - 1 : -1;
    const int nb_hi = (kk < BLKS_PER_SHOT - 1) ? b + 1 : -1;

    const float inv_dx = 1.0f / DXC;
    const int   gbase  = (z0 - 2) * NXPP;     // global offset of smem row 0

    unsigned  q      = *(volatile unsigned*)&g_flags[b * 32];   // replay-safe base
    unsigned* myflag = &g_flags[b * 32];

    // ---------- zero smem tiles (halos + pad cols stay 0 forever where unwritten) ----------
    for (int c = tid; c < 5 * FTILE; c += NTHR) sm[c] = 0.0f;

    // ---------- coefficient helper ----------
    auto coef = [&](int i, int j, float& dtrho, float& damp, float& lam, float& mu, float& l2mu) {
        int ip = min(max(i - NPML, 0), NZ - 1);
        int jp = min(max(j - NPML, 0), NX - 1);
        float vp  = Vp [ip * NX + jp];
        float vs  = Vs [ip * NX + jp];
        float den = Den[ip * NX + jp];
        float m   = Mask[i * NXP + j];
        vp  = m * vp  + (1.0f - m) * vp;
        vs  = m * vs  + (1.0f - m) * vs;
        den = m * den + (1.0f - m) * den;
        mu   = vs * vs * den * 1e-6f;
        lam  = (vp * vp - 2.0f * vs * vs) * den * 1e-6f;
        l2mu = lam + 2.0f * mu;
        dtrho = DTC / den;
        float a1 = (float)(NPML - i);
        float a2 = (float)(i - (NZP - 1 - NPML));
        float dz = fmaxf(a1, a2); dz = fminf(fmaxf(dz, 0.0f), (float)NPML) / (float)NPML;
        float b1 = (float)(NPML - j);
        float b2 = (float)(j - (NXP - 1 - NPML));
        float dxs = fmaxf(b1, b2); dxs = fminf(fmaxf(dxs, 0.0f), (float)NPML) / (float)NPML;
        damp = expf(-0.1f * (dz * dz + dxs * dxs));
    };

    // ---------- owned cells: boundary rows first (row order: z0, z1-1, z0+1, z1-2, mid) ----------
    int   soff[MAXC], fl[MAXC];
    float cdamp[MAXC], cdtrho[MAXC], clam[MAXC], cl2mu[MAXC], cmu[MAXC];

    const int sid  = ShotIds[s];
    const int srcx = NPML + 20 + sid * ((NX - 40) / NSHOTS);
    const float* stf = Stf + sid * NSTEPS;

    #pragma unroll
    for (int k = 0; k < MAXC; ++k) {
        int c  = tid + k * NTHR;
        int v  = (c < ncells);
        int cc = v ? c : 0;
        int rowk = cc / NXP;
        int j    = cc - rowk * NXP;
        int r = (rowk & 1) ? (nrows + 1 - ((rowk - 1) >> 1)) : (2 + (rowk >> 1));
        int i = z0 - 2 + r;

        soff[k] = r * SPITCH + j;

        int f = v ? F_VAL : 0;
        if (v && i == REC_Z && j >= NPML && j < NPML + NX) f |= F_REC;
        if (v && i == SRC_Z && j == srcx)                  f |= F_SRC;
        bool lo = (nb_lo >= 0), hi = (nb_hi >= 0);
        bool r2 = (r == 2), r3 = (r == 3), rN = (r == nrows), rN1 = (r == nrows + 1);
        if (v && ((lo && r2)          || (hi && rN1)))          f |= F_PXX;
        if (v && ((lo && (r2 || r3))  || (hi && rN1)))          f |= F_PZZ;
        if (v && ((lo && r2)          || (hi && (rN1 || rN))))  f |= F_PXZ;
        fl[k] = f;

        float dtr, dmp, lam, mu, l2mu;
        coef(i, j, dtr, dmp, lam, mu, l2mu);
        cdtrho[k] = dtr; cdamp[k] = dmp; clam[k] = lam; cmu[k] = mu; cl2mu[k] = l2mu;
    }

    // ---------- halo velocity cell (<=1 per thread): lo row z0-1, hi row z1 ----------
    int   h_soff = -1;
    float h_dtrho = 0.0f, h_damp = 0.0f;
    if (nb_lo >= 0 && tid < NXP) {
        h_soff = 1 * SPITCH + tid;
        float lam, mu, l2mu;
        coef(z0 - 1, tid, h_dtrho, h_damp, lam, mu, l2mu);
    } else if (nb_hi >= 0 && tid >= 512 && tid < 512 + NXP) {
        int j = tid - 512;
        h_soff = (nrows + 2) * SPITCH + j;
        float lam, mu, l2mu;
        coef(z1, j, h_dtrho, h_damp, lam, mu, l2mu);
    }

    __syncthreads();   // smem zero + setup done (block-local)

    double acc = 0.0;

    // ---- compute bodies ----
    auto vcell = [&](int k) {
        const int f = fl[k];
        if (!(f & F_VAL)) return;
        const int so = soff[k];
        float sxx_c = s_sxx[so];
        float sxx_r = s_sxx[so + 1];
        float sxz_c = s_sxz[so];
        float sxz_u = s_sxz[so - SPITCH];
        float sxz_l = s_sxz[so - 1];          // pad cols are 0 -> safe at j=0
        float szz_c = s_szz[so];
        float szz_d = s_szz[so + SPITCH];
        float nvx = (s_vx[so] + cdtrho[k] * ((sxx_r - sxx_c) + (sxz_c - sxz_u)) * inv_dx) * cdamp[k];
        float nvz = (s_vz[so] + cdtrho[k] * ((sxz_c - sxz_l) + (szz_d - szz_c)) * inv_dx) * cdamp[k];
        s_vx[so] = nvx;
        s_vz[so] = nvz;
        if (f & F_REC) acc += (double)nvx * (double)nvx;
    };

    // ---------------- time loop ----------------
    for (int t = 0; t < NSTEPS; ++t) {
        const int p = t & 1;
        float* __restrict__ bx  = g_bsxx[p][s];
        float* __restrict__ bz  = g_bszz[p][s];
        float* __restrict__ bxz = g_bsxz[p][s];

        // ===== velocity: owned + halo rows (halo == bit-identical recompute of neighbor's row) =====
        vcell(0); vcell(1); vcell(2);
        if (h_soff >= 0) {
            const int so = h_soff;
            float sxx_c = s_sxx[so];
            float sxx_r = s_sxx[so + 1];
            float sxz_c = s_sxz[so];
            float sxz_u = s_sxz[so - SPITCH];
            float sxz_l = s_sxz[so - 1];
            float szz_c = s_szz[so];
            float szz_d = s_szz[so + SPITCH];
            s_vx[so] = (s_vx[so] + h_dtrho * ((sxx_r - sxx_c) + (sxz_c - sxz_u)) * inv_dx) * h_damp;
            s_vz[so] = (s_vz[so] + h_dtrho * ((sxz_c - sxz_l) + (szz_d - szz_c)) * inv_dx) * h_damp;
        }
        __syncthreads();

        // ===== stress: boundary chunks first, publish inline =====
        #pragma unroll
        for (int k = 0; k < MAXC; ++k) {
            if (k == 2) {
                __syncthreads();                               // boundary rows complete
                ++q;
                if (tid == 0) st_release_u32(myflag, q);       // publish S(t)
            }
            const int f = fl[k];
            if (!(f & F_VAL)) continue;
            const int so = soff[k];

            float vx_c = s_vx[so];
            float vx_l = s_vx[so - 1];
            float vx_d = s_vx[so + SPITCH];
            float vz_c = s_vz[so];
            float vz_u = s_vz[so - SPITCH];
            float vz_r = s_vz[so + 1];

            float dvxdx = (vx_c - vx_l) * inv_dx;
            float dvzdz = (vz_c - vz_u) * inv_dx;

            float sxxn = (s_sxx[so] + DTC * (cl2mu[k] * dvxdx + clam[k]  * dvzdz)) * cdamp[k];
            float szzn = (s_szz[so] + DTC * (clam[k]  * dvxdx + cl2mu[k] * dvzdz)) * cdamp[k];
            float sxzn = (s_sxz[so] + DTC * cmu[k] * ((vx_d - vx_c) + (vz_r - vz_c)) * inv_dx) * cdamp[k];

            if (f & F_SRC) {
                float sv = stf[t] * DTC;
                sxxn += sv;
                szzn += sv;
            }

            s_sxx[so] = sxxn;
            s_szz[so] = szzn;
            s_sxz[so] = sxzn;

            if (f & F_PXX) __stcg(&bx [gbase + so], sxxn);
            if (f & F_PZZ) __stcg(&bz [gbase + so], szzn);
            if (f & F_PXZ) __stcg(&bxz[gbase + so], sxzn);
        }

        // ===== single handshake + import (used by NEXT step's velocity) =====
        if (tid == NTHR - 1) {
            if (nb_lo >= 0) wait_flag(&g_flags[nb_lo * 32], q);
            if (nb_hi >= 0) wait_flag(&g_flags[nb_hi * 32], q);
        }
        __syncthreads();   // flags observed + interior stress done

        for (int idx = tid; idx < 8 * NXP; idx += NTHR) {
            int seg = idx / NXP;
            int j   = idx - seg * NXP;
            if (seg < 4) {
                if (nb_lo < 0) continue;
                int gsrc = (z0 - 1) * NXPP + j;
                if      (seg == 0) s_sxx[SPITCH + j] = __ldcg(&bx [gsrc]);
                else if (seg == 1) s_sxz[SPITCH + j] = __ldcg(&bxz[gsrc]);
                else if (seg == 2) s_szz[SPITCH + j] = __ldcg(&bz [gsrc]);
                else               s_sxz[j]          = __ldcg(&bxz[gsrc - NXPP]);   // z0-2
            } else {
                if (nb_hi < 0) continue;
                int rh   = (nrows + 2) * SPITCH;
                int gsrc = z1 * NXPP + j;
                if      (seg == 4) s_sxx[rh + j]          = __ldcg(&bx [gsrc]);
                else if (seg == 5) s_sxz[rh + j]          = __ldcg(&bxz[gsrc]);
                else if (seg == 6) s_szz[rh + j]          = __ldcg(&bz [gsrc]);
                else               s_szz[rh + SPITCH + j] = __ldcg(&bz [gsrc + NXPP]); // z1+1
            }
        }
        __syncthreads();
    }

    // ---------------- deterministic reduction ----------------
    __shared__ double sh[NTHR];
    sh[tid] = acc;
    __syncthreads();
    for (int o = NTHR / 2; o > 0; o >>= 1) {
        if (tid < o) sh[tid] += sh[tid + o];
        __syncthreads();
    }

    __shared__ int is_last;
    if (tid == 0) {
        g_part[b] = sh[0];
        __threadfence();
        unsigned ticket = atomicAdd(&g_done, 1u);
        is_last = ((ticket + 1u) % NBLK == 0u) ? 1 : 0;
    }
    __syncthreads();

    if (is_last) {
        __threadfence();
        double a = 0.0;
        if (tid < NBLK) a = __ldcg(&g_part[tid]);
        sh[tid] = a;
        __syncthreads();
        for (int o = NTHR / 2; o > 0; o >>= 1) {
            if (tid < o) sh[tid] += sh[tid + o];
            __syncthreads();
        }
        if (tid == 0) out[0] = (float)(0.5 * sh[0]);
    }
}

// ---------------- launcher ----------------
extern "C" void kernel_launch(void* const* d_in, const int* in_sizes, int n_in,
                              void* d_out, int out_size)
{
    const float* Vp      = (const float*)d_in[0];
    const float* Vs      = (const float*)d_in[1];
    const float* Den     = (const float*)d_in[2];
    const float* Stf     = (const float*)d_in[3];
    const float* Mask    = (const float*)d_in[4];
    const int*   ShotIds = (const int*)  d_in[5];
    float*       out     = (float*)d_out;
    (void)in_sizes; (void)n_in; (void)out_size;

    static int smem_set = 0;
    if (!smem_set) {
        cudaFuncSetAttribute(fwi_persistent,
                             cudaFuncAttributeMaxDynamicSharedMemorySize, SMEM_DYN);
        smem_set = 1;
    }

    fwi_persistent<<<NBLK, NTHR, SMEM_DYN>>>(Vp, Vs, Den, Stf, Mask, ShotIds, out);
}

// round 7
// speedup vs baseline: 1.2407x; 1.2407x over previous
#include <cuda_runtime.h>

// ---------------- problem constants ----------------
#define NZ     300
#define NX     400
#define NPML   32
#define NZP    (NZ + 2*NPML)            // 364
#define NXP    (NX + 2*NPML)            // 464
#define NXPP   480                      // global row pitch (floats)
#define NSTEPS 200
#define NSHOTS 2
#define DXC    0.01f
#define DTC    0.001f
#define SRC_Z  (NPML + 2)               // 34
#define REC_Z  (NPML + 2)               // 34

#define FSZ (NZP * NXPP)

#define BLKS_PER_SHOT 74
#define NBLK   (NSHOTS * BLKS_PER_SHOT) // 148
#define NTHR   512
#define MAXC   5                        // 5*464/512 = 4.53 -> 5 chunks

// smem tile: row 0 = z0-1 (halo), rows 1..nrows owned, row nrows+1 = z1 (halo)
#define SROWS  7
#define SPITCH 480                      // == NXPP, so goff = (z0-1)*NXPP + soff
#define FTILE  (SROWS * SPITCH)
#define SMEM_DYN 122880                 // 120KB: > 67200 needed; forces 1 block/SM

// flag bits
#define F_VAL  1
#define F_REC  2
#define F_SRC  4
#define F_TOP  8     // r == 1     -> publish to lo
#define F_BOT  16    // r == nrows -> publish to hi

// ---------------- device state (static, no allocs) ----------------
// boundary-row exchange buffers (flag-gated; race-free per phase ordering)
__device__ float g_vx [NSHOTS][FSZ];
__device__ float g_vz [NSHOTS][FSZ];
__device__ float g_szz[NSHOTS][FSZ];
__device__ float g_sxz[NSHOTS][FSZ];

__device__ unsigned g_flags[NBLK * 32];   // monotonic, 128B apart
__device__ double   g_part[NBLK];
__device__ unsigned g_done = 0u;

__device__ __forceinline__ void st_release_u32(unsigned* p, unsigned v)
{
    asm volatile("st.release.gpu.global.u32 [%0], %1;" :: "l"(p), "r"(v) : "memory");
}
__device__ __forceinline__ unsigned ld_acquire_u32(const unsigned* p)
{
    unsigned v;
    asm volatile("ld.acquire.gpu.global.u32 %0, [%1];" : "=r"(v) : "l"(p) : "memory");
    return v;
}
__device__ __forceinline__ void wait_flag(const unsigned* f, unsigned q)
{
    while ((int)(ld_acquire_u32(f) - q) < 0) { }
}

__global__ void __launch_bounds__(NTHR)
fwi_persistent(const float* __restrict__ Vp,
               const float* __restrict__ Vs,
               const float* __restrict__ Den,
               const float* __restrict__ Stf,
               const float* __restrict__ Mask,
               const int*   __restrict__ ShotIds,
               float*       __restrict__ out)
{
    extern __shared__ float sm[];
    float* __restrict__ s_vx  = sm;
    float* __restrict__ s_vz  = sm + 1 * FTILE;
    float* __restrict__ s_sxx = sm + 2 * FTILE;
    float* __restrict__ s_szz = sm + 3 * FTILE;
    float* __restrict__ s_sxz = sm + 4 * FTILE;

    const int b   = blockIdx.x;
    const int s   = b / BLKS_PER_SHOT;
    const int kk  = b - s * BLKS_PER_SHOT;
    const int z0  = (kk * NZP) / BLKS_PER_SHOT;
    const int z1  = ((kk + 1) * NZP) / BLKS_PER_SHOT;
    const int nrows  = z1 - z0;
    const int ncells = nrows * NXP;
    const int tid = threadIdx.x;

    const int nb_lo = (kk > 0)                 ? b - 1 : -1;
    const int nb_hi = (kk < BLKS_PER_SHOT - 1) ? b + 1 : -1;

    float* __restrict__ vxg  = g_vx [s];
    float* __restrict__ vzg  = g_vz [s];
    float* __restrict__ szzg = g_szz[s];
    float* __restrict__ sxzg = g_sxz[s];

    const int gbase = (z0 - 1) * NXPP;     // global offset of smem row 0

    unsigned  q      = *(volatile unsigned*)&g_flags[b * 32];   // replay-safe base
    unsigned* myflag = &g_flags[b * 32];

    // ---------- zero smem tiles ----------
    for (int c = tid; c < 5 * FTILE; c += NTHR) sm[c] = 0.0f;

    // ---------- per-thread cells (boundary rows first), coeffs + fields in regs ----------
    int   soff[MAXC], fl[MAXC];
    float cdamp[MAXC], cdtrho[MAXC], cA[MAXC], cB[MAXC], cC[MAXC];
    float rvx[MAXC], rvz[MAXC], rsxx[MAXC], rszz[MAXC], rsxz[MAXC];

    const int sid  = ShotIds[s];
    const int srcx = NPML + 20 + sid * ((NX - 40) / NSHOTS);
    const float* stf = Stf + sid * NSTEPS;

    const float inv_dx = 1.0f / DXC;

    #pragma unroll
    for (int k = 0; k < MAXC; ++k) {
        int c  = tid + k * NTHR;
        int v  = (c < ncells);
        int cc = v ? c : 0;
        int r, j;
        if (cc < NXP)          { r = 1;     j = cc; }
        else if (cc < 2 * NXP) { r = nrows; j = cc - NXP; }
        else { int c2 = cc - 2 * NXP; int rr = c2 / NXP; r = 2 + rr; j = c2 - rr * NXP; }
        int i = z0 - 1 + r;

        soff[k] = r * SPITCH + j;

        int f = v ? F_VAL : 0;
        if (v && i == REC_Z && j >= NPML && j < NPML + NX) f |= F_REC;
        if (v && i == SRC_Z && j == srcx)                  f |= F_SRC;
        if (v && r == 1)      f |= F_TOP;
        if (v && r == nrows)  f |= F_BOT;
        fl[k] = f;

        int ip = min(max(i - NPML, 0), NZ - 1);
        int jp = min(max(j - NPML, 0), NX - 1);
        float vp  = Vp [ip * NX + jp];
        float vs  = Vs [ip * NX + jp];
        float den = Den[ip * NX + jp];
        float m   = Mask[i * NXP + j];
        vp  = m * vp  + (1.0f - m) * vp;
        vs  = m * vs  + (1.0f - m) * vs;
        den = m * den + (1.0f - m) * den;

        float mu  = vs * vs * den * 1e-6f;
        float lam = (vp * vp - 2.0f * vs * vs) * den * 1e-6f;
        cA[k] = DTC * (lam + 2.0f * mu) * inv_dx;
        cB[k] = DTC * lam * inv_dx;
        cC[k] = DTC * mu  * inv_dx;
        cdtrho[k] = DTC / den * inv_dx;

        float a1 = (float)(NPML - i);
        float a2 = (float)(i - (NZP - 1 - NPML));
        float dz = fmaxf(a1, a2); dz = fminf(fmaxf(dz, 0.0f), (float)NPML) / (float)NPML;
        float b1 = (float)(NPML - j);
        float b2 = (float)(j - (NXP - 1 - NPML));
        float dxs = fmaxf(b1, b2); dxs = fminf(fmaxf(dxs, 0.0f), (float)NPML) / (float)NPML;
        cdamp[k] = expf(-0.1f * (dz * dz + dxs * dxs));

        rvx[k] = 0.0f; rvz[k] = 0.0f; rsxx[k] = 0.0f; rszz[k] = 0.0f; rsxz[k] = 0.0f;
    }

    __syncthreads();   // smem zero + setup done (block-local)

    double acc = 0.0;

    const int haloT = 0;
    const int haloB = (nrows + 1) * SPITCH;
    const bool imp  = (tid < NXP);

    // ---- compute bodies (centers from registers, neighbors from smem) ----
    auto vcell = [&](int k) {
        const int f = fl[k];
        if (!(f & F_VAL)) return;
        const int so = soff[k];
        float sxx_r = s_sxx[so + 1];
        float sxz_u = s_sxz[so - SPITCH];
        float sxz_l = s_sxz[so - 1];
        float szz_d = s_szz[so + SPITCH];
        float nvx = (rvx[k] + cdtrho[k] * ((sxx_r - rsxx[k]) + (rsxz[k] - sxz_u))) * cdamp[k];
        float nvz = (rvz[k] + cdtrho[k] * ((rsxz[k] - sxz_l) + (szz_d - rszz[k]))) * cdamp[k];
        rvx[k] = nvx;
        rvz[k] = nvz;
        s_vx[so] = nvx;
        s_vz[so] = nvz;
        if (f & F_TOP) __stcg(&vxg[gbase + so], nvx);
        if (f & F_BOT) __stcg(&vzg[gbase + so], nvz);
        if (f & F_REC) acc += (double)nvx * (double)nvx;
    };

    auto scell = [&](int k, int t) {
        const int f = fl[k];
        if (!(f & F_VAL)) return;
        const int so = soff[k];
        float vx_l = s_vx[so - 1];
        float vx_d = s_vx[so + SPITCH];
        float vz_u = s_vz[so - SPITCH];
        float vz_r = s_vz[so + 1];
        float dx = rvx[k] - vx_l;
        float dz = rvz[k] - vz_u;
        float sxxn = (rsxx[k] + cA[k] * dx + cB[k] * dz) * cdamp[k];
        float szzn = (rszz[k] + cB[k] * dx + cA[k] * dz) * cdamp[k];
        float sxzn = (rsxz[k] + cC[k] * ((vx_d - rvx[k]) + (vz_r - rvz[k]))) * cdamp[k];
        if (f & F_SRC) {
            float sv = stf[t] * DTC;
            sxxn += sv;
            szzn += sv;
        }
        rsxx[k] = sxxn; rszz[k] = szzn; rsxz[k] = sxzn;
        s_sxx[so] = sxxn;
        s_szz[so] = szzn;
        s_sxz[so] = sxzn;
        if (f & F_TOP) __stcg(&szzg[gbase + so], szzn);
        if (f & F_BOT) __stcg(&sxzg[gbase + so], sxzn);
    };

    // ---------------- time loop ----------------
    for (int t = 0; t < NSTEPS; ++t) {
        // ===== velocity half-step =====
        vcell(0); vcell(1);                       // boundary rows complete here
        __syncthreads();
        ++q;
        if (tid == 0) st_release_u32(myflag, q);  // publish V(t)
        vcell(2);

        float hT = 0.0f, hB = 0.0f;
        if (imp) {                                 // wait short, ldcg hides behind k=3,4
            if (nb_lo >= 0) wait_flag(&g_flags[nb_lo * 32], q);
            if (nb_hi >= 0) wait_flag(&g_flags[nb_hi * 32], q);
            if (nb_lo >= 0) hT = __ldcg(&vzg[(z0 - 1) * NXPP + tid]);
            if (nb_hi >= 0) hB = __ldcg(&vxg[ z1      * NXPP + tid]);
        }

        vcell(3); vcell(4);

        if (imp) {
            if (nb_lo >= 0) s_vz[haloT + tid] = hT;
            if (nb_hi >= 0) s_vx[haloB + tid] = hB;
        }
        __syncthreads();

        // ===== stress half-step =====
        scell(0, t); scell(1, t);
        __syncthreads();
        ++q;
        if (tid == 0) st_release_u32(myflag, q);  // publish S(t)
        scell(2, t);

        hT = 0.0f; hB = 0.0f;
        if (imp) {
            if (nb_lo >= 0) wait_flag(&g_flags[nb_lo * 32], q);
            if (nb_hi >= 0) wait_flag(&g_flags[nb_hi * 32], q);
            if (nb_lo >= 0) hT = __ldcg(&sxzg[(z0 - 1) * NXPP + tid]);
            if (nb_hi >= 0) hB = __ldcg(&szzg[ z1      * NXPP + tid]);
        }

        scell(3, t); scell(4, t);

        if (imp) {
            if (nb_lo >= 0) s_sxz[haloT + tid] = hT;
            if (nb_hi >= 0) s_szz[haloB + tid] = hB;
        }
        __syncthreads();
    }

    // ---------------- deterministic reduction ----------------
    __shared__ double sh[NTHR];
    sh[tid] = acc;
    __syncthreads();
    for (int o = NTHR / 2; o > 0; o >>= 1) {
        if (tid < o) sh[tid] += sh[tid + o];
        __syncthreads();
    }

    __shared__ int is_last;
    if (tid == 0) {
        g_part[b] = sh[0];
        __threadfence();
        unsigned ticket = atomicAdd(&g_done, 1u);
        is_last = ((ticket + 1u) % NBLK == 0u) ? 1 : 0;
    }
    __syncthreads();

    if (is_last) {
        __threadfence();
        double a = 0.0;
        if (tid < NBLK) a = __ldcg(&g_part[tid]);
        sh[tid] = a;
        __syncthreads();
        for (int o = NTHR / 2; o > 0; o >>= 1) {
            if (tid < o) sh[tid] += sh[tid + o];
            __syncthreads();
        }
        if (tid == 0) out[0] = (float)(0.5 * sh[0]);
    }
}

// ---------------- launcher ----------------
extern "C" void kernel_launch(void* const* d_in, const int* in_sizes, int n_in,
                              void* d_out, int out_size)
{
    const float* Vp      = (const float*)d_in[0];
    const float* Vs      = (const float*)d_in[1];
    const float* Den     = (const float*)d_in[2];
    const float* Stf     = (const float*)d_in[3];
    const float* Mask    = (const float*)d_in[4];
    const int*   ShotIds = (const int*)  d_in[5];
    float*       out     = (float*)d_out;
    (void)in_sizes; (void)n_in; (void)out_size;

    static int smem_set = 0;
    if (!smem_set) {
        cudaFuncSetAttribute(fwi_persistent,
                             cudaFuncAttributeMaxDynamicSharedMemorySize, SMEM_DYN);
        smem_set = 1;
    }

    fwi_persistent<<<NBLK, NTHR, SMEM_DYN>>>(Vp, Vs, Den, Stf, Mask, ShotIds, out);
}

// round 8
// speedup vs baseline: 1.3281x; 1.0705x over previous
#include <cuda_runtime.h>

// ---------------- problem constants ----------------
#define NZ     300
#define NX     400
#define NPML   32
#define NZP    (NZ + 2*NPML)            // 364
#define NXP    (NX + 2*NPML)            // 464
#define NXPP   480                      // global row pitch (floats)
#define NSTEPS 200
#define NSHOTS 2
#define DXC    0.01f
#define DTC    0.001f
#define SRC_Z  (NPML + 2)               // 34
#define REC_Z  (NPML + 2)               // 34

#define FSZ (NZP * NXPP)

#define BLKS_PER_SHOT 74
#define NBLK   (NSHOTS * BLKS_PER_SHOT) // 148
#define NTHR   1024
#define MAXC   2                        // cell-PAIRS per thread (max 1160/1024 -> 2)
#define NXH    232                      // pairs per row (464/2)

// smem tile: row 0 = z0-1 (halo), rows 1..nrows owned, row nrows+1 = z1 (halo)
#define SROWS  7
#define SPITCH 480                      // == NXPP
#define FTILE  (SROWS * SPITCH)
#define SMEM_DYN (5 * FTILE * 4)        // 67200 B

// flag bits
#define F_VAL   1
#define F_TOP   2     // r == 1     -> publish to lo
#define F_BOT   4     // r == nrows -> publish to hi
#define F_REC0  8
#define F_REC1  16
#define F_SRC0  32
#define F_SRC1  64

// ---------------- device state (static, no allocs) ----------------
__device__ float g_vx [NSHOTS][FSZ];
__device__ float g_vz [NSHOTS][FSZ];
__device__ float g_szz[NSHOTS][FSZ];
__device__ float g_sxz[NSHOTS][FSZ];

__device__ unsigned g_flags[NBLK * 32];   // monotonic, 128B apart
__device__ double   g_part[NBLK];
__device__ unsigned g_done = 0u;

__device__ __forceinline__ void st_release_u32(unsigned* p, unsigned v)
{
    asm volatile("st.release.gpu.global.u32 [%0], %1;" :: "l"(p), "r"(v) : "memory");
}
__device__ __forceinline__ unsigned ld_acquire_u32(const unsigned* p)
{
    unsigned v;
    asm volatile("ld.acquire.gpu.global.u32 %0, [%1];" : "=r"(v) : "l"(p) : "memory");
    return v;
}
__device__ __forceinline__ void wait_flag(const unsigned* f, unsigned q)
{
    while ((int)(ld_acquire_u32(f) - q) < 0) { }
}

__global__ void __launch_bounds__(NTHR, 1)
fwi_persistent(const float* __restrict__ Vp,
               const float* __restrict__ Vs,
               const float* __restrict__ Den,
               const float* __restrict__ Stf,
               const float* __restrict__ Mask,
               const int*   __restrict__ ShotIds,
               float*       __restrict__ out)
{
    extern __shared__ float sm[];
    float* __restrict__ s_vx  = sm;
    float* __restrict__ s_vz  = sm + 1 * FTILE;
    float* __restrict__ s_sxx = sm + 2 * FTILE;
    float* __restrict__ s_szz = sm + 3 * FTILE;
    float* __restrict__ s_sxz = sm + 4 * FTILE;

    const int b   = blockIdx.x;
    const int s   = b / BLKS_PER_SHOT;
    const int kk  = b - s * BLKS_PER_SHOT;
    const int z0  = (kk * NZP) / BLKS_PER_SHOT;
    const int z1  = ((kk + 1) * NZP) / BLKS_PER_SHOT;
    const int nrows = z1 - z0;
    const int tid = threadIdx.x;

    const int nb_lo = (kk > 0)                 ? b - 1 : -1;
    const int nb_hi = (kk < BLKS_PER_SHOT - 1) ? b + 1 : -1;

    float* __restrict__ vxg  = g_vx [s];
    float* __restrict__ vzg  = g_vz [s];
    float* __restrict__ szzg = g_szz[s];
    float* __restrict__ sxzg = g_sxz[s];

    const int gbase = (z0 - 1) * NXPP;     // global offset of smem row 0

    unsigned  q      = *(volatile unsigned*)&g_flags[b * 32];   // replay-safe base
    unsigned* myflag = &g_flags[b * 32];

    // ---------- zero smem tiles (halos + pad cols stay 0 where never written) ----------
    for (int c = tid; c < 5 * FTILE; c += NTHR) sm[c] = 0.0f;

    // ---------- coefficient helper (per scalar cell) ----------
    auto coef = [&](int i, int j, float& dtr, float& dmp, float& a, float& bb, float& cc) {
        int ip = min(max(i - NPML, 0), NZ - 1);
        int jp = min(max(j - NPML, 0), NX - 1);
        float vp  = Vp [ip * NX + jp];
        float vs  = Vs [ip * NX + jp];
        float den = Den[ip * NX + jp];
        float m   = Mask[i * NXP + j];
        vp  = m * vp  + (1.0f - m) * vp;
        vs  = m * vs  + (1.0f - m) * vs;
        den = m * den + (1.0f - m) * den;
        float mu  = vs * vs * den * 1e-6f;
        float lam = (vp * vp - 2.0f * vs * vs) * den * 1e-6f;
        const float inv_dx = 1.0f / DXC;
        a   = DTC * (lam + 2.0f * mu) * inv_dx;
        bb  = DTC * lam * inv_dx;
        cc  = DTC * mu  * inv_dx;
        dtr = (DTC / den) * inv_dx;
        float a1 = (float)(NPML - i);
        float a2 = (float)(i - (NZP - 1 - NPML));
        float dz = fmaxf(a1, a2); dz = fminf(fmaxf(dz, 0.0f), (float)NPML) / (float)NPML;
        float b1 = (float)(NPML - j);
        float b2 = (float)(j - (NXP - 1 - NPML));
        float dxs = fmaxf(b1, b2); dxs = fminf(fmaxf(dxs, 0.0f), (float)NPML) / (float)NPML;
        dmp = expf(-0.1f * (dz * dz + dxs * dxs));
    };

    // ---------- per-thread cell-pair assignment ----------
    // pair ids: 0..231 -> row r=1 ; 232..463 -> row r=nrows ; 464.. -> interior rows 2..nrows-1
    // chunk0: tid<464 -> boundary pair tid ; tid in [464,464+c0) -> interior pair tid
    // chunk1: tid < ni-c0 -> interior pair 464+c0+tid    (c0 = min(ni,232))
    const int ncells2 = nrows * NXH;
    const int ni = ncells2 - 2 * NXH;
    const int c0 = ni < NXH ? ni : NXH;

    int    soff[MAXC], fl[MAXC];
    float2 cdamp[MAXC], cdtrho[MAXC], cA[MAXC], cB[MAXC], cC[MAXC];

    const int sid  = ShotIds[s];
    const int srcx = NPML + 20 + sid * ((NX - 40) / NSHOTS);
    const float* stf = Stf + sid * NSTEPS;

    #pragma unroll
    for (int k = 0; k < MAXC; ++k) {
        int cell = -1;
        if (k == 0) {
            if (tid < 2 * NXH) cell = tid;
            else if (tid - 2 * NXH < c0) cell = tid;     // interior pairs 464..464+c0-1
        } else {
            if (tid < ni - c0) cell = 2 * NXH + c0 + tid;
        }

        int v = (cell >= 0);
        int cc2 = v ? cell : 0;
        int r, jj;
        if (cc2 < NXH)            { r = 1;     jj = cc2; }
        else if (cc2 < 2 * NXH)   { r = nrows; jj = cc2 - NXH; }
        else { int e = cc2 - 2 * NXH; int rr = e / NXH; r = 2 + rr; jj = e - rr * NXH; }
        int j = 2 * jj;
        int i = z0 - 1 + r;

        soff[k] = r * SPITCH + j;

        int f = v ? F_VAL : 0;
        if (v && r == 1)     f |= F_TOP;
        if (v && r == nrows) f |= F_BOT;
        if (v && i == REC_Z) {
            if (j     >= NPML && j     < NPML + NX) f |= F_REC0;
            if (j + 1 >= NPML && j + 1 < NPML + NX) f |= F_REC1;
        }
        if (v && i == SRC_Z) {
            if (j == srcx)     f |= F_SRC0;
            if (j + 1 == srcx) f |= F_SRC1;
        }
        fl[k] = f;

        float d0, m0, a0, b0, c0f, d1, m1, a1, b1, c1f;
        coef(i, j,     d0, m0, a0, b0, c0f);
        coef(i, j + 1, d1, m1, a1, b1, c1f);
        cdtrho[k] = make_float2(d0, d1);
        cdamp[k]  = make_float2(m0, m1);
        cA[k]     = make_float2(a0, a1);
        cB[k]     = make_float2(b0, b1);
        cC[k]     = make_float2(c0f, c1f);
    }

    __syncthreads();   // smem zero + setup done (block-local)

    double acc = 0.0;

    const int haloT = 0;
    const int haloB = (nrows + 1) * SPITCH;

    // ---- vectorized compute bodies (per-lane math identical to scalar) ----
    auto vcell = [&](int k) {
        const int f = fl[k];
        if (!(f & F_VAL)) return;
        const int so = soff[k];

        float2 sxx_c = *(float2*)&s_sxx[so];
        float  sxx_2 = s_sxx[so + 2];
        float2 sxz_c = *(float2*)&s_sxz[so];
        float  sxz_m = s_sxz[so - 1];                 // pad col / prev-row pad = 0
        float2 sxz_u = *(float2*)&s_sxz[so - SPITCH];
        float2 szz_c = *(float2*)&s_szz[so];
        float2 szz_d = *(float2*)&s_szz[so + SPITCH];
        float2 vx    = *(float2*)&s_vx[so];
        float2 vz    = *(float2*)&s_vz[so];

        vx.x = (vx.x + cdtrho[k].x * ((sxx_c.y - sxx_c.x) + (sxz_c.x - sxz_u.x))) * cdamp[k].x;
        vx.y = (vx.y + cdtrho[k].y * ((sxx_2   - sxx_c.y) + (sxz_c.y - sxz_u.y))) * cdamp[k].y;
        vz.x = (vz.x + cdtrho[k].x * ((sxz_c.x - sxz_m  ) + (szz_d.x - szz_c.x))) * cdamp[k].x;
        vz.y = (vz.y + cdtrho[k].y * ((sxz_c.y - sxz_c.x) + (szz_d.y - szz_c.y))) * cdamp[k].y;

        *(float2*)&s_vx[so] = vx;
        *(float2*)&s_vz[so] = vz;

        if (f & F_TOP) __stcg((float2*)&vxg[gbase + so], vx);
        if (f & F_BOT) __stcg((float2*)&vzg[gbase + so], vz);
        if (f & F_REC0) acc += (double)vx.x * (double)vx.x;
        if (f & F_REC1) acc += (double)vx.y * (double)vx.y;
    };

    auto scell = [&](int k, int t) {
        const int f = fl[k];
        if (!(f & F_VAL)) return;
        const int so = soff[k];

        float2 vx_c = *(float2*)&s_vx[so];
        float  vx_m = s_vx[so - 1];
        float2 vx_d = *(float2*)&s_vx[so + SPITCH];
        float2 vz_c = *(float2*)&s_vz[so];
        float  vz_2 = s_vz[so + 2];
        float2 vz_u = *(float2*)&s_vz[so - SPITCH];
        float2 sxx  = *(float2*)&s_sxx[so];
        float2 szz  = *(float2*)&s_szz[so];
        float2 sxz  = *(float2*)&s_sxz[so];

        float dx0 = vx_c.x - vx_m;
        float dx1 = vx_c.y - vx_c.x;
        float dz0 = vz_c.x - vz_u.x;
        float dz1 = vz_c.y - vz_u.y;

        sxx.x = (sxx.x + cA[k].x * dx0 + cB[k].x * dz0) * cdamp[k].x;
        sxx.y = (sxx.y + cA[k].y * dx1 + cB[k].y * dz1) * cdamp[k].y;
        szz.x = (szz.x + cB[k].x * dx0 + cA[k].x * dz0) * cdamp[k].x;
        szz.y = (szz.y + cB[k].y * dx1 + cA[k].y * dz1) * cdamp[k].y;
        sxz.x = (sxz.x + cC[k].x * ((vx_d.x - vx_c.x) + (vz_c.y - vz_c.x))) * cdamp[k].x;
        sxz.y = (sxz.y + cC[k].y * ((vx_d.y - vx_c.y) + (vz_2   - vz_c.y))) * cdamp[k].y;

        if (f & F_SRC0) { float sv = stf[t] * DTC; sxx.x += sv; szz.x += sv; }
        if (f & F_SRC1) { float sv = stf[t] * DTC; sxx.y += sv; szz.y += sv; }

        *(float2*)&s_sxx[so] = sxx;
        *(float2*)&s_szz[so] = szz;
        *(float2*)&s_sxz[so] = sxz;

        if (f & F_TOP) __stcg((float2*)&szzg[gbase + so], szz);
        if (f & F_BOT) __stcg((float2*)&sxzg[gbase + so], sxz);
    };

    // ---------------- time loop ----------------
    for (int t = 0; t < NSTEPS; ++t) {
        // ===== velocity half-step =====
        vcell(0);                                  // all boundary pairs are in chunk 0
        __syncthreads();
        ++q;
        if (tid == 0) st_release_u32(myflag, q);   // publish V(t)
        vcell(1);                                  // 464 interior pairs hide handshake

        if (nb_lo >= 0 && tid < NXP) {
            wait_flag(&g_flags[nb_lo * 32], q);
            s_vz[haloT + tid] = __ldcg(&vzg[(z0 - 1) * NXPP + tid]);
        }
        if (nb_hi >= 0 && tid >= 512 && tid < 512 + NXP) {
            wait_flag(&g_flags[nb_hi * 32], q);
            s_vx[haloB + (tid - 512)] = __ldcg(&vxg[z1 * NXPP + (tid - 512)]);
        }
        __syncthreads();

        // ===== stress half-step =====
        scell(0, t);
        __syncthreads();
        ++q;
        if (tid == 0) st_release_u32(myflag, q);   // publish S(t)
        scell(1, t);

        if (nb_lo >= 0 && tid < NXP) {
            wait_flag(&g_flags[nb_lo * 32], q);
            s_sxz[haloT + tid] = __ldcg(&sxzg[(z0 - 1) * NXPP + tid]);
        }
        if (nb_hi >= 0 && tid >= 512 && tid < 512 + NXP) {
            wait_flag(&g_flags[nb_hi * 32], q);
            s_szz[haloB + (tid - 512)] = __ldcg(&szzg[z1 * NXPP + (tid - 512)]);
        }
        __syncthreads();
    }

    // ---------------- deterministic reduction ----------------
    __shared__ double sh[NTHR];
    sh[tid] = acc;
    __syncthreads();
    for (int o = NTHR / 2; o > 0; o >>= 1) {
        if (tid < o) sh[tid] += sh[tid + o];
        __syncthreads();
    }

    __shared__ int is_last;
    if (tid == 0) {
        g_part[b] = sh[0];
        __threadfence();
        unsigned ticket = atomicAdd(&g_done, 1u);
        is_last = ((ticket + 1u) % NBLK == 0u) ? 1 : 0;
    }
    __syncthreads();

    if (is_last) {
        __threadfence();
        double a = 0.0;
        if (tid < NBLK) a = __ldcg(&g_part[tid]);
        sh[tid] = a;
        __syncthreads();
        for (int o = NTHR / 2; o > 0; o >>= 1) {
            if (tid < o) sh[tid] += sh[tid + o];
            __syncthreads();
        }
        if (tid == 0) out[0] = (float)(0.5 * sh[0]);
    }
}

// ---------------- launcher ----------------
extern "C" void kernel_launch(void* const* d_in, const int* in_sizes, int n_in,
                              void* d_out, int out_size)
{
    const float* Vp      = (const float*)d_in[0];
    const float* Vs      = (const float*)d_in[1];
    const float* Den     = (const float*)d_in[2];
    const float* Stf     = (const float*)d_in[3];
    const float* Mask    = (const float*)d_in[4];
    const int*   ShotIds = (const int*)  d_in[5];
    float*       out     = (float*)d_out;
    (void)in_sizes; (void)n_in; (void)out_size;

    static int smem_set = 0;
    if (!smem_set) {
        cudaFuncSetAttribute(fwi_persistent,
                             cudaFuncAttributeMaxDynamicSharedMemorySize, SMEM_DYN);
        smem_set = 1;
    }

    fwi_persistent<<<NBLK, NTHR, SMEM_DYN>>>(Vp, Vs, Den, Stf, Mask, ShotIds, out);
}

// round 9
// speedup vs baseline: 1.7810x; 1.3409x over previous
#include <cuda_runtime.h>

// ---------------- problem constants ----------------
#define NZ     300
#define NX     400
#define NPML   32
#define NZP    (NZ + 2*NPML)            // 364
#define NXP    (NX + 2*NPML)            // 464
#define NXPP   480                      // global row pitch (floats)
#define NSTEPS 200
#define NSHOTS 2
#define DXC    0.01f
#define DTC    0.001f
#define SRC_Z  (NPML + 2)               // 34
#define REC_Z  (NPML + 2)               // 34

#define FSZ (NZP * NXPP)

#define BLKS_PER_SHOT 74
#define NBLK   (NSHOTS * BLKS_PER_SHOT) // 148
#define NTHR   1024
#define MAXC   3                        // owned cells/thread (5*464/1024 -> 3)

// smem tile: row r <-> global row z0-2+r
//   r=0 guard(0), r=1 = z0-1 (vx/vz imported, sxz recomputed),
//   r=2..nrows+1 owned, r=nrows+2 = z1 (vx/vz imported, szz recomputed)
#define SROWS  8
#define SPITCH 480                      // == NXPP
#define FTILE  (SROWS * SPITCH)
#define SMEM_DYN (5 * FTILE * 4)        // 76800 B

// flag bits
#define F_VAL  1
#define F_REC  2
#define F_SRC  4
#define F_TOP  8     // r == 2        (row z0)   -> publish vx,vz to lo
#define F_BOT  16    // r == nrows+1  (row z1-1) -> publish vx,vz to hi

// ---------------- device state (static, no allocs) ----------------
// ONLY velocity boundary rows are exchanged now
__device__ float g_vx[NSHOTS][FSZ];
__device__ float g_vz[NSHOTS][FSZ];

__device__ unsigned g_flags[NBLK * 32];   // monotonic, 128B apart
__device__ double   g_part[NBLK];
__device__ unsigned g_done = 0u;

__device__ __forceinline__ void st_release_u32(unsigned* p, unsigned v)
{
    asm volatile("st.release.gpu.global.u32 [%0], %1;" :: "l"(p), "r"(v) : "memory");
}
__device__ __forceinline__ unsigned ld_acquire_u32(const unsigned* p)
{
    unsigned v;
    asm volatile("ld.acquire.gpu.global.u32 %0, [%1];" : "=r"(v) : "l"(p) : "memory");
    return v;
}
__device__ __forceinline__ void wait_flag(const unsigned* f, unsigned q)
{
    while ((int)(ld_acquire_u32(f) - q) < 0) { }
}

__global__ void __launch_bounds__(NTHR, 1)
fwi_persistent(const float* __restrict__ Vp,
               const float* __restrict__ Vs,
               const float* __restrict__ Den,
               const float* __restrict__ Stf,
               const float* __restrict__ Mask,
               const int*   __restrict__ ShotIds,
               float*       __restrict__ out)
{
    extern __shared__ float sm[];
    float* __restrict__ s_vx  = sm;
    float* __restrict__ s_vz  = sm + 1 * FTILE;
    float* __restrict__ s_sxx = sm + 2 * FTILE;
    float* __restrict__ s_szz = sm + 3 * FTILE;
    float* __restrict__ s_sxz = sm + 4 * FTILE;

    const int b   = blockIdx.x;
    const int s   = b / BLKS_PER_SHOT;
    const int kk  = b - s * BLKS_PER_SHOT;
    const int z0  = (kk * NZP) / BLKS_PER_SHOT;
    const int z1  = ((kk + 1) * NZP) / BLKS_PER_SHOT;
    const int nrows  = z1 - z0;
    const int ncells = nrows * NXP;
    const int tid = threadIdx.x;

    const int nb_lo = (kk > 0)                 ? b - 1 : -1;
    const int nb_hi = (kk < BLKS_PER_SHOT - 1) ? b + 1 : -1;

    float* __restrict__ vxg = g_vx[s];
    float* __restrict__ vzg = g_vz[s];

    const int gbase = (z0 - 2) * NXPP;     // global offset of smem row 0

    unsigned  q      = *(volatile unsigned*)&g_flags[b * 32];   // replay-safe base
    unsigned* myflag = &g_flags[b * 32];

    // ---------- zero smem tiles (guards, halos, pad cols start/stay 0 where unwritten) ----------
    for (int c = tid; c < 5 * FTILE; c += NTHR) sm[c] = 0.0f;

    // ---------- coefficient helper ----------
    auto coef = [&](int i, int j, float& dtr, float& dmp, float& a, float& bb, float& cc) {
        int ip = min(max(i - NPML, 0), NZ - 1);
        int jp = min(max(j - NPML, 0), NX - 1);
        float vp  = Vp [ip * NX + jp];
        float vs  = Vs [ip * NX + jp];
        float den = Den[ip * NX + jp];
        float m   = Mask[i * NXP + j];
        vp  = m * vp  + (1.0f - m) * vp;
        vs  = m * vs  + (1.0f - m) * vs;
        den = m * den + (1.0f - m) * den;
        float mu  = vs * vs * den * 1e-6f;
        float lam = (vp * vp - 2.0f * vs * vs) * den * 1e-6f;
        const float inv_dx = 1.0f / DXC;
        a   = DTC * (lam + 2.0f * mu) * inv_dx;
        bb  = DTC * lam * inv_dx;
        cc  = DTC * mu  * inv_dx;
        dtr = (DTC / den) * inv_dx;
        float a1 = (float)(NPML - i);
        float a2 = (float)(i - (NZP - 1 - NPML));
        float dz = fmaxf(a1, a2); dz = fminf(fmaxf(dz, 0.0f), (float)NPML) / (float)NPML;
        float b1 = (float)(NPML - j);
        float b2 = (float)(j - (NXP - 1 - NPML));
        float dxs = fmaxf(b1, b2); dxs = fminf(fmaxf(dxs, 0.0f), (float)NPML) / (float)NPML;
        dmp = expf(-0.1f * (dz * dz + dxs * dxs));
    };

    // ---------- owned cells, boundary rows first ----------
    int   soff[MAXC], fl[MAXC];
    float cdamp[MAXC], cdtrho[MAXC], cA[MAXC], cB[MAXC], cC[MAXC];

    const int sid  = ShotIds[s];
    const int srcx = NPML + 20 + sid * ((NX - 40) / NSHOTS);
    const float* stf = Stf + sid * NSTEPS;

    #pragma unroll
    for (int k = 0; k < MAXC; ++k) {
        int c  = tid + k * NTHR;
        int v  = (c < ncells);
        int cc2 = v ? c : 0;
        int r, j;
        if (cc2 < NXP)          { r = 2;         j = cc2; }
        else if (cc2 < 2 * NXP) { r = nrows + 1; j = cc2 - NXP; }
        else { int e = cc2 - 2 * NXP; int rr = e / NXP; r = 3 + rr; j = e - rr * NXP; }
        int i = z0 - 2 + r;

        soff[k] = r * SPITCH + j;

        int f = v ? F_VAL : 0;
        if (v && i == REC_Z && j >= NPML && j < NPML + NX) f |= F_REC;
        if (v && i == SRC_Z && j == srcx)                  f |= F_SRC;
        if (v && r == 2)          f |= F_TOP;
        if (v && r == nrows + 1)  f |= F_BOT;
        fl[k] = f;

        float dtr, dmp, a, bb, cc;
        coef(i, j, dtr, dmp, a, bb, cc);
        cdtrho[k] = dtr; cdamp[k] = dmp; cA[k] = a; cB[k] = bb; cC[k] = cc;
    }

    // ---------- stress-halo recompute cells (<=1 per thread each side) ----------
    // top: sxz(z0-1); bottom: szz(z1)
    const bool topH = (nb_lo >= 0 && tid < NXP);
    const bool botH = (nb_hi >= 0 && tid >= 512 && tid < 512 + NXP);
    float hC = 0.0f, hdampT = 0.0f;            // top: mu coeff + damp
    float hA = 0.0f, hB = 0.0f, hdampB = 0.0f; // bottom: lam2mu, lam + damp
    bool  srcB = false;
    if (topH) {
        float dtr, a, bb;
        coef(z0 - 1, tid, dtr, hdampT, a, bb, hC);
    }
    if (botH) {
        int j = tid - 512;
        float dtr, cc;
        coef(z1, j, dtr, hdampB, hA, hB, cc);
        srcB = (z1 == SRC_Z && j == srcx);
    }

    __syncthreads();   // smem zero + setup done (block-local)

    double acc = 0.0;

    const int topSO = 1 * SPITCH;              // row z0-1
    const int botSO = (nrows + 2) * SPITCH;    // row z1

    // ---- velocity body (owned rows only) ----
    auto vcell = [&](int k) {
        const int f = fl[k];
        if (!(f & F_VAL)) return;
        const int so = soff[k];
        float sxx_c = s_sxx[so];
        float sxx_r = s_sxx[so + 1];
        float sxz_c = s_sxz[so];
        float sxz_u = s_sxz[so - SPITCH];   // r=1 is recomputed halo
        float sxz_l = s_sxz[so - 1];        // pad cols are 0
        float szz_c = s_szz[so];
        float szz_d = s_szz[so + SPITCH];   // r=nrows+2 is recomputed halo
        float nvx = (s_vx[so] + cdtrho[k] * ((sxx_r - sxx_c) + (sxz_c - sxz_u))) * cdamp[k];
        float nvz = (s_vz[so] + cdtrho[k] * ((sxz_c - sxz_l) + (szz_d - szz_c))) * cdamp[k];
        s_vx[so] = nvx;
        s_vz[so] = nvz;
        if (f & (F_TOP | F_BOT)) {
            __stcg(&vxg[gbase + so], nvx);
            __stcg(&vzg[gbase + so], nvz);
        }
        if (f & F_REC) acc += (double)nvx * (double)nvx;
    };

    // ---- stress body (owned rows) ----
    auto scell = [&](int k, int t) {
        const int f = fl[k];
        if (!(f & F_VAL)) return;
        const int so = soff[k];
        float vx_c = s_vx[so];
        float vx_l = s_vx[so - 1];
        float vx_d = s_vx[so + SPITCH];     // r=nrows+2 imported
        float vz_c = s_vz[so];
        float vz_u = s_vz[so - SPITCH];     // r=1 imported
        float vz_r = s_vz[so + 1];
        float dx = vx_c - vx_l;
        float dz = vz_c - vz_u;
        float sxxn = (s_sxx[so] + cA[k] * dx + cB[k] * dz) * cdamp[k];
        float szzn = (s_szz[so] + cB[k] * dx + cA[k] * dz) * cdamp[k];
        float sxzn = (s_sxz[so] + cC[k] * ((vx_d - vx_c) + (vz_r - vz_c))) * cdamp[k];
        if (f & F_SRC) {
            float sv = stf[t] * DTC;
            sxxn += sv;
            szzn += sv;
        }
        s_sxx[so] = sxxn;
        s_szz[so] = szzn;
        s_sxz[so] = sxzn;
    };

    // ---------------- time loop ----------------
    for (int t = 0; t < NSTEPS; ++t) {
        // ===== velocity phase =====
        vcell(0);                                  // boundary rows z0, z1-1 (+spill interior)
        __syncthreads();
        ++q;
        if (tid == 0) st_release_u32(myflag, q);   // publish V(t) boundary
        vcell(1); vcell(2);                        // interior = mattress for the handshake

        // import neighbor velocity rows (lo publishes its z1-1 = z0-1; hi its z0 = z1)
        float hvx = 0.0f, hvz = 0.0f;
        if (topH) {
            wait_flag(&g_flags[nb_lo * 32], q);
            hvx = __ldcg(&vxg[(z0 - 1) * NXPP + tid]);
            hvz = __ldcg(&vzg[(z0 - 1) * NXPP + tid]);
        }
        if (botH) {
            int j = tid - 512;
            wait_flag(&g_flags[nb_hi * 32], q);
            hvx = __ldcg(&vxg[z1 * NXPP + j]);
            hvz = __ldcg(&vzg[z1 * NXPP + j]);
        }
        if (topH) { s_vx[topSO + tid] = hvx; s_vz[topSO + tid] = hvz; }
        if (botH) { int j = tid - 512; s_vx[botSO + j] = hvx; s_vz[botSO + j] = hvz; }
        __syncthreads();   // all velocity (owned + halos) ready

        // ===== stress phase (owned) + stress-halo recompute =====
        scell(0, t); scell(1, t); scell(2, t);

        if (topH) {   // sxz(z0-1): bit-identical recompute of lo neighbor's row
            const int so = topSO + tid;
            float v = (s_sxz[so] + hC * ((s_vx[so + SPITCH] - s_vx[so])
                                       + (s_vz[so + 1]      - s_vz[so]))) * hdampT;
            s_sxz[so] = v;
        }
        if (botH) {   // szz(z1): bit-identical recompute of hi neighbor's row
            const int j  = tid - 512;
            const int so = botSO + j;
            float dx = s_vx[so] - s_vx[so - 1];
            float dz = s_vz[so] - s_vz[so - SPITCH];
            float v = (s_szz[so] + hB * dx + hA * dz) * hdampB;
            if (srcB) v += stf[t] * DTC;
            s_szz[so] = v;
        }
        __syncthreads();
    }

    // ---------------- deterministic reduction ----------------
    __shared__ double sh[NTHR];
    sh[tid] = acc;
    __syncthreads();
    for (int o = NTHR / 2; o > 0; o >>= 1) {
        if (tid < o) sh[tid] += sh[tid + o];
        __syncthreads();
    }

    __shared__ int is_last;
    if (tid == 0) {
        g_part[b] = sh[0];
        __threadfence();
        unsigned ticket = atomicAdd(&g_done, 1u);
        is_last = ((ticket + 1u) % NBLK == 0u) ? 1 : 0;
    }
    __syncthreads();

    if (is_last) {
        __threadfence();
        double a = 0.0;
        if (tid < NBLK) a = __ldcg(&g_part[tid]);
        sh[tid] = a;
        __syncthreads();
        for (int o = NTHR / 2; o > 0; o >>= 1) {
            if (tid < o) sh[tid] += sh[tid + o];
            __syncthreads();
        }
        if (tid == 0) out[0] = (float)(0.5 * sh[0]);
    }
}

// ---------------- launcher ----------------
extern "C" void kernel_launch(void* const* d_in, const int* in_sizes, int n_in,
                              void* d_out, int out_size)
{
    const float* Vp      = (const float*)d_in[0];
    const float* Vs      = (const float*)d_in[1];
    const float* Den     = (const float*)d_in[2];
    const float* Stf     = (const float*)d_in[3];
    const float* Mask    = (const float*)d_in[4];
    const int*   ShotIds = (const int*)  d_in[5];
    float*       out     = (float*)d_out;
    (void)in_sizes; (void)n_in; (void)out_size;

    static int smem_set = 0;
    if (!smem_set) {
        cudaFuncSetAttribute(fwi_persistent,
                             cudaFuncAttributeMaxDynamicSharedMemorySize, SMEM_DYN);
        smem_set = 1;
    }

    fwi_persistent<<<NBLK, NTHR, SMEM_DYN>>>(Vp, Vs, Den, Stf, Mask, ShotIds, out);
}